// round 11
// baseline (speedup 1.0000x reference)
#include <cuda_runtime.h>

#define FULLMASK 0xffffffffu
#define NEGC (-1000000000.0f)
#define FLR  (1e-30f)

__device__ float g_beta[256 * 128 * 128 * 3];   // beta scratch (50.3 MB)

__device__ __forceinline__ float lse2(float a, float b) {
    float mx = fmaxf(a, b);
    float mn = fminf(a, b);
    return mx + __logf(1.0f + __expf(mn - mx));
}
__device__ __forceinline__ float fmax3(float a, float b, float c) {
    return fmaxf(fmaxf(a, b), c);
}
__device__ __forceinline__ void relstore(int* p, int v) {
    asm volatile("st.release.cta.b32 [%0], %1;" :: "l"(p), "r"(v) : "memory");
}
__device__ __forceinline__ int acqload(int* p) {
    int v; asm volatile("ld.acquire.cta.b32 %0, [%1];" : "=r"(v) : "l"(p) : "memory");
    return v;
}

// One CTA (16 warps) per batch. Warps 0-7: forward alpha, segment s = w owns
// cols 16s..16s+15 (lanes 16-31 shadow lanes 0-15; stores guarded). Left->right
// mailbox chain per row. Warps 8-15: beta lattice (independent of alpha),
// segment v = 15-w, scan pos p = 16v + lane -> col 127-p, right->left mailbox
// chain, beta written to g_beta. Then __syncthreads + coalesced combine:
// out = alpha + beta - logZ.
__global__ void __launch_bounds__(512, 1)
fb_kernel(const float* __restrict__ theta, const float* __restrict__ Aall,
          float* __restrict__ out)
{
    __shared__ float fm[7][128], fx[7][128], fy[7][128];   // fwd mailboxes
    __shared__ int   ff[7][128];
    __shared__ float bu0s[7][128], bu2s[7][128];           // beta mailboxes
    __shared__ int   bf[7][128];
    __shared__ float shlogZ;

    const int tid  = threadIdx.x;
    const int w    = tid >> 5;
    const int lane = tid & 31;
    const int sl   = lane & 15;       // segment lane (lanes 16-31 shadow 0-15)
    const int b    = blockIdx.x;

    for (int j = tid; j < 7 * 128; j += 512) {
        (&ff[0][0])[j] = 0;
        (&bf[0][0])[j] = 0;
    }
    __syncthreads();

    const float* Ab = Aall + (size_t)b * 9;
    const float A02 = Ab[2], A12 = Ab[5], A20 = Ab[6], A21 = Ab[7], A22 = Ab[8];
    float E[9];
#pragma unroll
    for (int t = 0; t < 9; t++) E[t] = __expf(Ab[t]);
    const float eM0 = E[0], eM1 = E[3], eM2 = E[6];   // exp(A[:,0])
    const float eX0 = E[1], eX1 = E[4], eX2 = E[7];   // exp(A[:,1])

    const size_t base = (size_t)b * 49152;
    const float* th = theta + base;
    float* po = out + base;
    float* pb = g_beta + base;

    if (w < 8) {
        // ====================== FORWARD (alpha) ======================
        const int s = w;
        const int col = s * 16 + sl;
        const int off = col * 3;           // float offset within a 384-float row
        float pm = NEGC, px = NEGC, py = NEGC;
        float la0 = NEGC, la1 = NEGC, la2 = NEGC;

        float t0 = th[off], t1 = th[off + 1], t2 = th[off + 2];
        for (int i = 0; i < 128; i++) {
            float n0, n1, n2;
            if (i < 127) {
                int r = (i + 1) * 384 + off;
                n0 = th[r]; n1 = th[r + 1]; n2 = th[r + 2];
            }

            float hm = NEGC, hx = NEGC, hy = NEGC;
            float dM = NEGC, dX = NEGC, dY = NEGC;
            if (s > 0) {
                if (acqload(&ff[s - 1][i]) == 0) {
                    while (acqload(&ff[s - 1][i]) == 0) { __nanosleep(32); }
                }
                hm = fm[s - 1][i]; hx = fx[s - 1][i]; hy = fy[s - 1][i];
                if (i > 0) { dM = fm[s - 1][i - 1]; dX = fx[s - 1][i - 1]; dY = fy[s - 1][i - 1]; }
            }

            // shared-exp rep of own prev-row triple
            float r0 = fmax3(pm, px, py);
            float Em = __expf(pm - r0), Ex = __expf(px - r0), Ey = __expf(py - r0);
            // col-1 prev-row rep
            float rs  = __shfl_up_sync(FULLMASK, r0, 1);
            float Ems = __shfl_up_sync(FULLMASK, Em, 1);
            float Exs = __shfl_up_sync(FULLMASK, Ex, 1);
            float Eys = __shfl_up_sync(FULLMASK, Ey, 1);
            if (sl == 0) {
                if (s == 0) { rs = NEGC; Ems = 0.f; Exs = 0.f; Eys = 0.f; }
                else {
                    rs = fmax3(dM, dX, dY);
                    Ems = __expf(dM - rs); Exs = __expf(dX - rs); Eys = __expf(dY - rs);
                }
            }

            float lm = rs + __logf(fmaf(eM0, Ems, fmaf(eM1, Exs, fmaf(eM2, Eys, FLR))));
            if (s == 0 && i == 0 && sl == 0) lm = 0.0f;   // start cell (0,0,match)
            float m = t0 + lm;
            float x = t1 + r0 + __logf(fmaf(eX0, Em, fmaf(eX1, Ex, fmaf(eX2, Ey, FLR))));

            float mnb = __shfl_up_sync(FULLMASK, m, 1);
            float xnb = __shfl_up_sync(FULLMASK, x, 1);
            if (sl == 0) { mnb = (s == 0) ? NEGC : hm; xnb = (s == 0) ? NEGC : hx; }

            float c = t2 + lse2(mnb + A02, xnb + A12);
            float d = t2 + A22;

            float C = c, D = d;
#pragma unroll
            for (int off2 = 1; off2 < 16; off2 <<= 1) {
                float Cu = __shfl_up_sync(FULLMASK, C, off2);
                float Du = __shfl_up_sync(FULLMASK, D, off2);
                if (sl >= off2) { C = lse2(C, D + Cu); D += Du; }
            }
            float Ce = __shfl_up_sync(FULLMASK, C, 1);
            float De = __shfl_up_sync(FULLMASK, D, 1);
            float seed = (s == 0) ? NEGC : hy;
            float yin = (sl == 0) ? seed : lse2(Ce, De + seed);
            float y = lse2(c, d + yin);

            if (lane < 16) {
                int wo = i * 384 + off;
                po[wo] = m; po[wo + 1] = x; po[wo + 2] = y;
            }

            if (s < 7 && lane == 15) {
                fm[s][i] = m; fx[s][i] = x; fy[s][i] = y;
                relstore(&ff[s][i], 1);
            }
            if (i == 127) { la0 = m; la1 = x; la2 = y; }

            pm = m; px = x; py = y;
            if (i < 127) { t0 = n0; t1 = n1; t2 = n2; }
        }
        if (s == 7) {   // logZ from alpha(127,127,:) held in lane 15
            la0 = __shfl_sync(FULLMASK, la0, 15);
            la1 = __shfl_sync(FULLMASK, la1, 15);
            la2 = __shfl_sync(FULLMASK, la2, 15);
            float r = fmax3(la0, la1, la2);
            float lz = r + __logf(__expf(la0 - r) + __expf(la1 - r) + __expf(la2 - r));
            if (lane == 15) shlogZ = lz;
        }
    } else {
        // ====================== BETA (independent lattice) ======================
        const int wl = w - 8;                 // 0..7
        const int v = 7 - wl;                 // v=0 is the rightmost (producer) seg
        const int col = 16 * wl + 15 - sl;    // scan pos p = 16v+sl -> col = 127-p
        const int off = col * 3;
        float u0p = NEGC, u1p = NEGC;

        float t0 = th[127 * 384 + off], t1 = th[127 * 384 + off + 1], t2 = th[127 * 384 + off + 2];
        for (int i = 127; i >= 0; i--) {
            float n0, n1, n2;
            if (i > 0) {
                int r = (i - 1) * 384 + off;
                n0 = th[r]; n1 = th[r + 1]; n2 = th[r + 2];
            }

            float seed = NEGC, u0ext = NEGC;
            if (v > 0) {
                if (acqload(&bf[v - 1][i]) == 0) {
                    while (acqload(&bf[v - 1][i]) == 0) { __nanosleep(32); }
                }
                seed  = bu2s[v - 1][i];
                u0ext = (i < 127) ? bu0s[v - 1][i + 1] : NEGC;
            }

            float u0n = __shfl_up_sync(FULLMASK, u0p, 1);
            if (sl == 0) u0n = (v == 0) ? NEGC : u0ext;

            const bool lastcell = (v == 0 && sl == 0 && i == 127);
            float c = t2 + lse2(A20 + u0n, A21 + u1p);
            float d = t2 + A22;
            if (lastcell) { c = t2; d = NEGC; }   // beta(127,127)=0

            float C = c, D = d;
#pragma unroll
            for (int off2 = 1; off2 < 16; off2 <<= 1) {
                float Cu = __shfl_up_sync(FULLMASK, C, off2);
                float Du = __shfl_up_sync(FULLMASK, D, off2);
                if (sl >= off2) { C = lse2(C, D + Cu); D += Du; }
            }
            float Ce = __shfl_up_sync(FULLMASK, C, 1);
            float De = __shfl_up_sync(FULLMASK, D, 1);
            float yin = (sl == 0) ? seed : lse2(Ce, De + seed);

            float wr = yin;   // u2 at col j+1 (exclusive), current row
            float rr = fmax3(u0n, u1p, wr);
            float e0 = __expf(u0n - rr), e1 = __expf(u1p - rr), e2 = __expf(wr - rr);
            float bb0 = rr + __logf(fmaf(E[0], e0, fmaf(E[1], e1, fmaf(E[2], e2, FLR))));
            float bb1 = rr + __logf(fmaf(E[3], e0, fmaf(E[4], e1, fmaf(E[5], e2, FLR))));
            float bb2 = rr + __logf(fmaf(E[6], e0, fmaf(E[7], e1, fmaf(E[8], e2, FLR))));
            if (lastcell) { bb0 = 0.f; bb1 = 0.f; bb2 = 0.f; }

            if (lane < 16) {
                int ro = i * 384 + off;
                pb[ro] = bb0; pb[ro + 1] = bb1; pb[ro + 2] = bb2;
            }

            float nu0 = bb0 + t0;
            float nu1 = bb1 + t1;

            if (v < 7 && lane == 15) {
                bu0s[v][i] = nu0;
                bu2s[v][i] = lse2(c, d + yin);   // inclusive u2 at this column
                relstore(&bf[v][i], 1);
            }
            u0p = nu0; u1p = nu1;
            if (i > 0) { t0 = n0; t1 = n1; t2 = n2; }
        }
    }

    // ====================== COMBINE ======================
    __syncthreads();
    const float lz = shlogZ;
    const float4* bp4 = reinterpret_cast<const float4*>(pb);
    float4* op4 = reinterpret_cast<float4*>(po);
#pragma unroll 4
    for (int t = tid; t < 12288; t += 512) {
        float4 a = op4[t];
        float4 bb = bp4[t];
        op4[t] = make_float4(a.x + bb.x - lz, a.y + bb.y - lz,
                             a.z + bb.z - lz, a.w + bb.w - lz);
    }
}

extern "C" void kernel_launch(void* const* d_in, const int* in_sizes, int n_in,
                              void* d_out, int out_size)
{
    const float* theta = (const float*)d_in[0];
    const float* A     = (const float*)d_in[1];
    float* out         = (float*)d_out;
    int B = in_sizes[1] / 9;   // 256
    fb_kernel<<<B, 512>>>(theta, A, out);
}

// round 12
// speedup vs baseline: 1.3249x; 1.3249x over previous
#include <cuda_runtime.h>

#define FULLMASK 0xffffffffu
#define NEGC (-1000000000.0f)
#define FLR  (1e-30f)
#define BIGNEG (-3.0e38f)

__device__ float g_beta[256 * 128 * 128 * 3];   // beta scratch (50.3 MB)

__device__ __forceinline__ float lse2(float a, float b) {
    float mx = fmaxf(a, b);
    float mn = fminf(a, b);
    return mx + __logf(1.0f + __expf(mn - mx));
}
__device__ __forceinline__ float fmax3(float a, float b, float c) {
    return fmaxf(fmaxf(a, b), c);
}
__device__ __forceinline__ void relstore(int* p, int v) {
    asm volatile("st.release.cta.b32 [%0], %1;" :: "l"(p), "r"(v) : "memory");
}
__device__ __forceinline__ int acqload(int* p) {
    int v; asm volatile("ld.acquire.cta.b32 %0, [%1];" : "=r"(v) : "l"(p) : "memory");
    return v;
}

// One CTA (8 warps) per batch. Warps 0-3: forward alpha (cols 32s..32s+31,
// 1 col/lane, left->right mailbox chain) -> out. Warps 4-7: beta lattice
// (independent), right->left chain -> g_beta. y-recurrence solved per row via
// single-reference softmax scan: y_j = S_j + LSE(base_j, aux), S = prefix-sum
// of d (ADD scan), base = R + log(prefix-sum of exp(c-S-R)). Then combine.
__global__ void __launch_bounds__(256, 1)
fb_kernel(const float* __restrict__ theta, const float* __restrict__ Aall,
          float* __restrict__ out)
{
    __shared__ float fm[3][128], fx[3][128], fy[3][128];   // fwd mailboxes
    __shared__ int   ff[3][128];
    __shared__ float bu0s[3][128], bu2s[3][128];           // beta mailboxes
    __shared__ int   bf[3][128];
    __shared__ float shlogZ;

    const int tid  = threadIdx.x;
    const int w    = tid >> 5;
    const int lane = tid & 31;
    const int b    = blockIdx.x;

    for (int j = tid; j < 3 * 128; j += 256) {
        (&ff[0][0])[j] = 0;
        (&bf[0][0])[j] = 0;
    }
    __syncthreads();

    const float* Ab = Aall + (size_t)b * 9;
    const float A02 = Ab[2], A12 = Ab[5], A20 = Ab[6], A21 = Ab[7], A22 = Ab[8];
    float E[9];
#pragma unroll
    for (int t = 0; t < 9; t++) E[t] = __expf(Ab[t]);
    const float eM0 = E[0], eM1 = E[3], eM2 = E[6];   // exp(A[:,0])
    const float eX0 = E[1], eX1 = E[4], eX2 = E[7];   // exp(A[:,1])

    const size_t base_off = (size_t)b * 49152;
    const float* th = theta + base_off;
    float* po = out + base_off;
    float* pb = g_beta + base_off;

    if (w < 4) {
        // ====================== FORWARD (alpha) ======================
        const int s = w;
        const int col = s * 32 + lane;
        const int off = col * 3;
        float pm = NEGC, px = NEGC, py = NEGC;
        float dM = NEGC, dX = NEGC, dY = NEGC;   // neighbor row i-1 boundary (regs)
        float la0 = NEGC, la1 = NEGC, la2 = NEGC;

        float t0 = th[off], t1 = th[off + 1], t2 = th[off + 2];
        for (int i = 0; i < 128; i++) {
            float n0, n1, n2;
            if (i < 127) {
                int r = (i + 1) * 384 + off;
                n0 = th[r]; n1 = th[r + 1]; n2 = th[r + 2];
            }

            // ---------- EARLY (mailbox-independent) ----------
            float r0 = fmax3(pm, px, py);
            float Em = __expf(pm - r0), Ex = __expf(px - r0), Ey = __expf(py - r0);
            float rs  = __shfl_up_sync(FULLMASK, r0, 1);
            float Ems = __shfl_up_sync(FULLMASK, Em, 1);
            float Exs = __shfl_up_sync(FULLMASK, Ex, 1);
            float Eys = __shfl_up_sync(FULLMASK, Ey, 1);
            if (lane == 0) {
                if (s == 0) { rs = NEGC; Ems = 0.f; Exs = 0.f; Eys = 0.f; }
                else {
                    rs = fmax3(dM, dX, dY);
                    Ems = __expf(dM - rs); Exs = __expf(dX - rs); Eys = __expf(dY - rs);
                }
            }

            float lm = rs + __logf(fmaf(eM0, Ems, fmaf(eM1, Exs, fmaf(eM2, Eys, FLR))));
            if (s == 0 && i == 0 && lane == 0) lm = 0.0f;   // start cell (0,0,match)
            float m = t0 + lm;
            float x = t1 + r0 + __logf(fmaf(eX0, Em, fmaf(eX1, Ex, fmaf(eX2, Ey, FLR))));

            float mnb = __shfl_up_sync(FULLMASK, m, 1);
            float xnb = __shfl_up_sync(FULLMASK, x, 1);
            float c = t2 + lse2(mnb + A02, xnb + A12);   // lane0 garbage (excluded)
            float d = t2 + A22;

            float S = d;                                  // inclusive prefix sum of d
#pragma unroll
            for (int o = 1; o < 32; o <<= 1) {
                float tS = __shfl_up_sync(FULLMASK, S, o);
                if (lane >= o) S += tS;
            }
            float e = c - S;
            float em = (lane == 0) ? BIGNEG : e;
#pragma unroll
            for (int o = 16; o > 0; o >>= 1)
                em = fmaxf(em, __shfl_xor_sync(FULLMASK, em, o));
            float R = em;                                 // max over lanes 1..31
            float Ee = (lane == 0) ? 0.0f : __expf(e - R);
            float ss = Ee;                                // prefix sum of exps
#pragma unroll
            for (int o = 1; o < 32; o <<= 1) {
                float tS = __shfl_up_sync(FULLMASK, ss, o);
                if (lane >= o) ss += tS;
            }
            float bse = (lane == 0) ? NEGC : (R + __logf(ss + FLR));
            float t2b = __shfl_sync(FULLMASK, t2, 0);     // lane0's theta_y

            // ---------- LATE (needs mailbox slot i) ----------
            float hm = NEGC, hx = NEGC, hy = NEGC;
            if (s > 0) {
                if (acqload(&ff[s - 1][i]) == 0) {
                    while (acqload(&ff[s - 1][i]) == 0) { __nanosleep(32); }
                }
                hm = fm[s - 1][i]; hx = fx[s - 1][i]; hy = fy[s - 1][i];
            }
            float c0 = t2b + lse2(hm + A02, hx + A12);    // lane0 cell, exact
            float aux = lse2(c0 - (t2b + A22), hy);       // e0 merged with seed
            float y = S + lse2(bse, aux);

            int wo = i * 384 + off;
            po[wo] = m; po[wo + 1] = x; po[wo + 2] = y;

            if (s < 3 && lane == 31) {
                fm[s][i] = m; fx[s][i] = x; fy[s][i] = y;
                relstore(&ff[s][i], 1);
            }
            if (i == 127) { la0 = m; la1 = x; la2 = y; }

            pm = m; px = x; py = y;
            dM = hm; dX = hx; dY = hy;
            if (i < 127) { t0 = n0; t1 = n1; t2 = n2; }
        }
        if (s == 3) {   // logZ from alpha(127,127,:) held in lane 31
            la0 = __shfl_sync(FULLMASK, la0, 31);
            la1 = __shfl_sync(FULLMASK, la1, 31);
            la2 = __shfl_sync(FULLMASK, la2, 31);
            float r = fmax3(la0, la1, la2);
            float lz = r + __logf(__expf(la0 - r) + __expf(la1 - r) + __expf(la2 - r));
            if (lane == 31) shlogZ = lz;
        }
    } else {
        // ====================== BETA (independent lattice) ======================
        const int wl = w - 4;                 // 0..3
        const int v = 3 - wl;                 // v=0 is the rightmost (producer) seg
        const int col = 32 * wl + 31 - lane;  // scan pos p = 32v+lane -> col 127-p
        const int off = col * 3;
        float u0p = NEGC, u1p = NEGC;
        float u0ext = NEGC;                   // bu0s[v-1][i+1], carried in a reg

        float t0 = th[127 * 384 + off], t1 = th[127 * 384 + off + 1], t2 = th[127 * 384 + off + 2];
        for (int i = 127; i >= 0; i--) {
            float n0, n1, n2;
            if (i > 0) {
                int r = (i - 1) * 384 + off;
                n0 = th[r]; n1 = th[r + 1]; n2 = th[r + 2];
            }

            // ---------- EARLY ----------
            float u0n = __shfl_up_sync(FULLMASK, u0p, 1);
            if (lane == 0) u0n = u0ext;       // v==0: stays NEGC

            const bool lastcell = (v == 0 && lane == 0 && i == 127);
            float c = t2 + lse2(A20 + u0n, A21 + u1p);
            float d = t2 + A22;
            if (lastcell) { c = t2; d = 0.0f; }   // beta(127,127)=0; keep d finite

            float S = d;
#pragma unroll
            for (int o = 1; o < 32; o <<= 1) {
                float tS = __shfl_up_sync(FULLMASK, S, o);
                if (lane >= o) S += tS;
            }
            float e = c - S;
            float em = e;
#pragma unroll
            for (int o = 16; o > 0; o >>= 1)
                em = fmaxf(em, __shfl_xor_sync(FULLMASK, em, o));
            float R = em;
            float Ee = __expf(e - R);
            float ss = Ee;
#pragma unroll
            for (int o = 1; o < 32; o <<= 1) {
                float tS = __shfl_up_sync(FULLMASK, ss, o);
                if (lane >= o) ss += tS;
            }
            float bse = R + __logf(ss + FLR);

            // ---------- LATE ----------
            float seed = NEGC, nexu0 = NEGC;
            if (v > 0) {
                if (acqload(&bf[v - 1][i]) == 0) {
                    while (acqload(&bf[v - 1][i]) == 0) { __nanosleep(32); }
                }
                seed  = bu2s[v - 1][i];
                nexu0 = bu0s[v - 1][i];       // becomes u0ext for row i-1
            }
            float y = S + lse2(bse, seed);    // inclusive u2 at this column
            float wr = __shfl_up_sync(FULLMASK, y, 1);
            if (lane == 0) wr = seed;         // exclusive (u2 at col j+1)

            float rr = fmax3(u0n, u1p, wr);
            float e0 = __expf(u0n - rr), e1 = __expf(u1p - rr), e2 = __expf(wr - rr);
            float bb0 = rr + __logf(fmaf(E[0], e0, fmaf(E[1], e1, fmaf(E[2], e2, FLR))));
            float bb1 = rr + __logf(fmaf(E[3], e0, fmaf(E[4], e1, fmaf(E[5], e2, FLR))));
            float bb2 = rr + __logf(fmaf(E[6], e0, fmaf(E[7], e1, fmaf(E[8], e2, FLR))));
            if (lastcell) { bb0 = 0.f; bb1 = 0.f; bb2 = 0.f; }

            int ro = i * 384 + off;
            pb[ro] = bb0; pb[ro + 1] = bb1; pb[ro + 2] = bb2;

            float nu0 = bb0 + t0;
            float nu1 = bb1 + t1;

            if (v < 3 && lane == 31) {
                bu0s[v][i] = nu0;
                bu2s[v][i] = y;
                relstore(&bf[v][i], 1);
            }
            u0p = nu0; u1p = nu1; u0ext = nexu0;
            if (i > 0) { t0 = n0; t1 = n1; t2 = n2; }
        }
    }

    // ====================== COMBINE ======================
    __syncthreads();
    const float lz = shlogZ;
    const float4* bp4 = reinterpret_cast<const float4*>(pb);
    float4* op4 = reinterpret_cast<float4*>(po);
#pragma unroll 4
    for (int t = tid; t < 12288; t += 256) {
        float4 a = op4[t];
        float4 bb = bp4[t];
        op4[t] = make_float4(a.x + bb.x - lz, a.y + bb.y - lz,
                             a.z + bb.z - lz, a.w + bb.w - lz);
    }
}

extern "C" void kernel_launch(void* const* d_in, const int* in_sizes, int n_in,
                              void* d_out, int out_size)
{
    const float* theta = (const float*)d_in[0];
    const float* A     = (const float*)d_in[1];
    float* out         = (float*)d_out;
    int B = in_sizes[1] / 9;   // 256
    fb_kernel<<<B, 256>>>(theta, A, out);
}